// round 17
// baseline (speedup 1.0000x reference)
#include <cuda_runtime.h>
#include <math.h>
#include <stdint.h>

#define B_ 1024
#define T_ 128
#define F_ 32
#define E_ 16
#define H_ 20
#define G_ 80      // 4*H
#define D_ 4096    // T*F

// scratch (__device__ globals; no allocations allowed)
__device__ float g_fc1[B_ * D_];   // relu(x_flat @ fc1_w + b)
__device__ float g_eo[E_ * B_];    // per-expert outputs

// ---------------- helpers -------------------------------------------------
__device__ __forceinline__ float sigmoidf_(float x) {
    float e = __expf(-x);
    float r;
    asm("rcp.approx.f32 %0, %1;" : "=f"(r) : "f"(1.0f + e));
    return r;
}
__device__ __forceinline__ uint32_t f2tf32(float x) {
    uint32_t r; asm("cvt.rna.tf32.f32 %0, %1;" : "=r"(r) : "f"(x)); return r;
}
// D += A(tf32) * B(tf32), m16n8k8  (fragment mapping validated by fc1)
__device__ __forceinline__ void mma_tf32(float* c, const uint32_t* a, const uint32_t* b) {
    asm("mma.sync.aligned.m16n8k8.row.col.f32.tf32.tf32.f32 "
        "{%0,%1,%2,%3},{%4,%5,%6,%7},{%8,%9},{%0,%1,%2,%3};"
        : "+f"(c[0]), "+f"(c[1]), "+f"(c[2]), "+f"(c[3])
        : "r"(a[0]), "r"(a[1]), "r"(a[2]), "r"(a[3]), "r"(b[0]), "r"(b[1]));
}

// ===========================================================================
// kFat: fc1 tf32 GEMM (blocks [0,512)) + tensor-core LSTM (blocks [512,1024))
// ===========================================================================
#define FC1_BLOCKS 512
#define LROWS 32
#define LSTM_BLOCKS (E_ * B_ / LROWS)   // 512

struct SFC {                        // fc1 tile buffers (~29.7 KB)
    uint32_t Ah[128][20];
    uint32_t Al[128][20];
    uint32_t Bh[16][72];
    uint32_t Bl[16][72];
};
struct SPL {                        // tensor-lstm buffers (~44 KB)
    uint2 Xp[LROWS][34];            // x_t {tf32hi, tf32lo}, BN'd; cols 0..31
    uint2 H1p[LROWS][26];           // h1 {hi,lo}; cols 0..19 live, 20..25 zero
    uint2 H2p[LROWS][26];
    float z1[LROWS][84];            // fp32 gate pre-activations (padded)
    float z2[LROWS][84];
    float bns[F_], bnh[F_];
};
union __align__(16) UA { SFC f; SPL p; };

__global__ void __launch_bounds__(320, 2) kFat(
    const float* __restrict__ x, const float* __restrict__ fc1_w,
    const float* __restrict__ fc1_b,
    const float* __restrict__ bn_gamma, const float* __restrict__ bn_beta,
    const float* __restrict__ bn_mean,  const float* __restrict__ bn_var,
    const float* __restrict__ k1, const float* __restrict__ r1,
    const float* __restrict__ b1,
    const float* __restrict__ k2, const float* __restrict__ r2,
    const float* __restrict__ b2,
    const float* __restrict__ dw, const float* __restrict__ db)
{
    __shared__ UA u;
    const int tid = threadIdx.x;
    const int lane = tid & 31;
    const int w = tid >> 5;              // warp id 0..9
    const int g  = lane >> 2;            // 0..7
    const int tg = lane & 3;             // 0..3

    if (blockIdx.x < FC1_BLOCKS) {
        // ======== fc1: 128x64 block, mma.sync tf32 hi/lo split (proven, 3-pass)
        const int m0 = (blockIdx.x >> 6) * 128;
        const int n0 = (blockIdx.x & 63) * 64;
        const bool act = tid < 256;
        const int warp_m = w & 3;
        const int warp_n = (w >> 2) & 1;

        const int a_row = tid >> 1;
        const int a_kc  = (tid & 1) * 8;
        const int b_k   = tid >> 4;
        const int b_nc  = (tid & 15) * 4;

        const float* Ap = x + (size_t)(m0 + a_row) * D_ + a_kc;
        const float* Bp = fc1_w + (size_t)b_k * D_ + n0 + b_nc;

        float4 av0, av1, bv;
        if (act) {
            av0 = *(const float4*)Ap;
            av1 = *(const float4*)(Ap + 4);
            bv  = *(const float4*)Bp;
        }

        float c[2][4][4];
        #pragma unroll
        for (int mt = 0; mt < 2; mt++)
            #pragma unroll
            for (int nt = 0; nt < 4; nt++)
                #pragma unroll
                for (int j = 0; j < 4; j++) c[mt][nt][j] = 0.f;

        const int NS = D_ / 16;
        for (int s = 0; s < NS; s++) {
            if (act) {
                float af[8] = {av0.x, av0.y, av0.z, av0.w, av1.x, av1.y, av1.z, av1.w};
                uint32_t hh[8], ll[8];
                #pragma unroll
                for (int j = 0; j < 8; j++) {
                    uint32_t hi = f2tf32(af[j]);
                    float lo = af[j] - __uint_as_float(hi);
                    hh[j] = hi;
                    ll[j] = f2tf32(lo);
                }
                *(uint4*)&u.f.Ah[a_row][a_kc]     = make_uint4(hh[0], hh[1], hh[2], hh[3]);
                *(uint4*)&u.f.Ah[a_row][a_kc + 4] = make_uint4(hh[4], hh[5], hh[6], hh[7]);
                *(uint4*)&u.f.Al[a_row][a_kc]     = make_uint4(ll[0], ll[1], ll[2], ll[3]);
                *(uint4*)&u.f.Al[a_row][a_kc + 4] = make_uint4(ll[4], ll[5], ll[6], ll[7]);
                float bf[4] = {bv.x, bv.y, bv.z, bv.w};
                uint32_t bhh[4], bll[4];
                #pragma unroll
                for (int j = 0; j < 4; j++) {
                    uint32_t hi = f2tf32(bf[j]);
                    float lo = bf[j] - __uint_as_float(hi);
                    bhh[j] = hi;
                    bll[j] = f2tf32(lo);
                }
                *(uint4*)&u.f.Bh[b_k][b_nc] = make_uint4(bhh[0], bhh[1], bhh[2], bhh[3]);
                *(uint4*)&u.f.Bl[b_k][b_nc] = make_uint4(bll[0], bll[1], bll[2], bll[3]);
            }
            __syncthreads();
            if (act && s + 1 < NS) {
                av0 = *(const float4*)(Ap + (size_t)(s + 1) * 16);
                av1 = *(const float4*)(Ap + (size_t)(s + 1) * 16 + 4);
                bv  = *(const float4*)(Bp + (size_t)(s + 1) * 16 * D_);
            }
            if (act && w < 8) {
                #pragma unroll
                for (int kk = 0; kk < 16; kk += 8) {
                    uint32_t ah[2][4], al[2][4], bh[4][2], bl[4][2];
                    #pragma unroll
                    for (int mt = 0; mt < 2; mt++) {
                        const int ar = warp_m * 32 + mt * 16 + g;
                        ah[mt][0] = u.f.Ah[ar][kk + tg];
                        ah[mt][1] = u.f.Ah[ar + 8][kk + tg];
                        ah[mt][2] = u.f.Ah[ar][kk + tg + 4];
                        ah[mt][3] = u.f.Ah[ar + 8][kk + tg + 4];
                        al[mt][0] = u.f.Al[ar][kk + tg];
                        al[mt][1] = u.f.Al[ar + 8][kk + tg];
                        al[mt][2] = u.f.Al[ar][kk + tg + 4];
                        al[mt][3] = u.f.Al[ar + 8][kk + tg + 4];
                    }
                    #pragma unroll
                    for (int nt = 0; nt < 4; nt++) {
                        const int bc = warp_n * 32 + nt * 8 + g;
                        bh[nt][0] = u.f.Bh[kk + tg][bc];
                        bh[nt][1] = u.f.Bh[kk + tg + 4][bc];
                        bl[nt][0] = u.f.Bl[kk + tg][bc];
                        bl[nt][1] = u.f.Bl[kk + tg + 4][bc];
                    }
                    #pragma unroll
                    for (int mt = 0; mt < 2; mt++)
                        #pragma unroll
                        for (int nt = 0; nt < 4; nt++) {
                            mma_tf32(c[mt][nt], ah[mt], bh[nt]);
                            mma_tf32(c[mt][nt], ah[mt], bl[nt]);
                            mma_tf32(c[mt][nt], al[mt], bh[nt]);
                        }
                }
            }
            __syncthreads();
        }

        if (act && w < 8) {
            #pragma unroll
            for (int mt = 0; mt < 2; mt++) {
                #pragma unroll
                for (int nt = 0; nt < 4; nt++) {
                    const int row = m0 + warp_m * 32 + mt * 16 + g;
                    const int col = n0 + warp_n * 32 + nt * 8 + 2 * tg;
                    float2 bb = *(const float2*)&fc1_b[col];
                    float2 o0, o1;
                    o0.x = fmaxf(c[mt][nt][0] + bb.x, 0.f);
                    o0.y = fmaxf(c[mt][nt][1] + bb.y, 0.f);
                    o1.x = fmaxf(c[mt][nt][2] + bb.x, 0.f);
                    o1.y = fmaxf(c[mt][nt][3] + bb.y, 0.f);
                    *(float2*)&g_fc1[(size_t)row * D_ + col]       = o0;
                    *(float2*)&g_fc1[(size_t)(row + 8) * D_ + col] = o1;
                }
            }
        }
        return;
    }

    // ======== tensor-core LSTM: 32 rows, 10 warps, warp w -> cols [8w,8w+8)
    // 2-pass precision: A (x/h) hi/lo split; weights tf32-hi only.
    const int lb = blockIdx.x - FC1_BLOCKS;
    const int e = lb >> 5;                 // 32 blocks per expert
    const int row0 = (lb & 31) * LROWS;

    const int col  = 8 * w + g;          // B-frag column
    const int col0 = 8 * w + 2 * tg;     // C-frag column base

    // --- preload weight B-fragments (tf32-hi, registers, loop-invariant) ---
    uint32_t w1h[7][2], w2h[6][2];
    #pragma unroll
    for (int kt = 0; kt < 4; kt++) {
        const int ra = 8 * kt + tg, rb = ra + 4;
        w1h[kt][0] = f2tf32(k1[(e * F_ + ra) * G_ + col]);
        w1h[kt][1] = f2tf32(k1[(e * F_ + rb) * G_ + col]);
    }
    #pragma unroll
    for (int kt = 4; kt < 7; kt++) {
        const int ra = 8 * (kt - 4) + tg, rb = ra + 4;
        w1h[kt][0] = f2tf32(r1[(e * H_ + ra) * G_ + col]);
        w1h[kt][1] = f2tf32((rb < H_) ? r1[(e * H_ + rb) * G_ + col] : 0.f);
    }
    #pragma unroll
    for (int kt = 0; kt < 3; kt++) {
        const int ra = 8 * kt + tg, rb = ra + 4;
        w2h[kt][0] = f2tf32(k2[(e * H_ + ra) * G_ + col]);
        w2h[kt][1] = f2tf32((rb < H_) ? k2[(e * H_ + rb) * G_ + col] : 0.f);
    }
    #pragma unroll
    for (int kt = 3; kt < 6; kt++) {
        const int ra = 8 * (kt - 3) + tg, rb = ra + 4;
        w2h[kt][0] = f2tf32(r2[(e * H_ + ra) * G_ + col]);
        w2h[kt][1] = f2tf32((rb < H_) ? r2[(e * H_ + rb) * G_ + col] : 0.f);
    }
    const float bz1x = b1[e * G_ + col0], bz1y = b1[e * G_ + col0 + 1];
    const float bz2x = b2[e * G_ + col0], bz2y = b2[e * G_ + col0 + 1];

    // cell mapping: 640 cells/layer = 2/thread; cell k: (crow0+16k, cu0)
    const int crow0 = tid / H_;          // 0..15
    const int cu0   = tid - crow0 * H_;  // 0..19

    if (tid < F_) {
        float scv = bn_gamma[tid] * rsqrtf(bn_var[tid] + 1e-3f);
        u.p.bns[tid] = scv;
        u.p.bnh[tid] = bn_beta[tid] - bn_mean[tid] * scv;
    }
    for (int idx = tid; idx < 2 * LROWS * 26; idx += 320)
        ((uint2*)u.p.H1p)[idx] = make_uint2(0u, 0u);
    __syncthreads();

    // x stagers: 1024 slots = 4 per thread (4th only for tid<64);
    // slot q: row = (tid>>5) + 10q, feature f = tid&31 (same f for all q)
    const int sr = tid >> 5, sf = tid & 31;
    const float sc = u.p.bns[sf], sh = u.p.bnh[sf];
    const float* pxs[4];
    #pragma unroll
    for (int q = 0; q < 4; q++)
        pxs[q] = x + (size_t)(row0 + sr + 10 * q) * D_ + sf;
    const bool hasq3 = tid < 64;

    float xv[4];
    #pragma unroll
    for (int q = 0; q < 4; q++) {
        if (q < 3 || hasq3) {
            float v = pxs[q][0] * sc + sh;
            uint32_t hi = f2tf32(v);
            u.p.Xp[sr + 10 * q][sf] = make_uint2(hi, f2tf32(v - __uint_as_float(hi)));
            xv[q] = pxs[q][F_];
        }
    }
    __syncthreads();

    float c1[2] = {0.f, 0.f}, c2[2] = {0.f, 0.f};

    #define LOAD_AFRAG(arr, rbase, kbase)                                     \
        { uint2 q0 = u.p.arr[(rbase) + g][(kbase) + tg];                      \
          uint2 q1 = u.p.arr[(rbase) + g + 8][(kbase) + tg];                  \
          uint2 q2 = u.p.arr[(rbase) + g][(kbase) + tg + 4];                  \
          uint2 q3 = u.p.arr[(rbase) + g + 8][(kbase) + tg + 4];              \
          ah[0] = q0.x; ah[1] = q1.x; ah[2] = q2.x; ah[3] = q3.x;             \
          al[0] = q0.y; al[1] = q1.y; al[2] = q2.y; al[3] = q3.y; }

    for (int t = 0; t <= T_; t++) {
        // ---- phase A: tensor-core gate pre-activations (2 M-tiles each) ----
        uint32_t ah[4], al[4];
        if (t < T_) {                       // z1(t) = b1 + x_t@Wk1 + h1(t-1)@Wr1
            #pragma unroll
            for (int mt = 0; mt < 2; mt++) {
                const int rb = 16 * mt;
                float cfr[4] = {bz1x, bz1y, bz1x, bz1y};
                #pragma unroll
                for (int kt = 0; kt < 4; kt++) {
                    LOAD_AFRAG(Xp, rb, 8 * kt);
                    mma_tf32(cfr, ah, w1h[kt]);
                    mma_tf32(cfr, al, w1h[kt]);
                }
                #pragma unroll
                for (int kt = 4; kt < 7; kt++) {
                    LOAD_AFRAG(H1p, rb, 8 * (kt - 4));
                    mma_tf32(cfr, ah, w1h[kt]);
                    mma_tf32(cfr, al, w1h[kt]);
                }
                *(float2*)&u.p.z1[rb + g][col0]     = make_float2(cfr[0], cfr[1]);
                *(float2*)&u.p.z1[rb + g + 8][col0] = make_float2(cfr[2], cfr[3]);
            }
        }
        if (t >= 1) {                       // z2(t-1) = b2 + h1(t-1)@Wk2 + h2(t-2)@Wr2
            #pragma unroll
            for (int mt = 0; mt < 2; mt++) {
                const int rb = 16 * mt;
                float cfr[4] = {bz2x, bz2y, bz2x, bz2y};
                #pragma unroll
                for (int kt = 0; kt < 3; kt++) {
                    LOAD_AFRAG(H1p, rb, 8 * kt);
                    mma_tf32(cfr, ah, w2h[kt]);
                    mma_tf32(cfr, al, w2h[kt]);
                }
                #pragma unroll
                for (int kt = 3; kt < 6; kt++) {
                    LOAD_AFRAG(H2p, rb, 8 * (kt - 3));
                    mma_tf32(cfr, ah, w2h[kt]);
                    mma_tf32(cfr, al, w2h[kt]);
                }
                *(float2*)&u.p.z2[rb + g][col0]     = make_float2(cfr[0], cfr[1]);
                *(float2*)&u.p.z2[rb + g + 8][col0] = make_float2(cfr[2], cfr[3]);
            }
        }
        __syncthreads();

        // ---- phase B: cells (2/layer/thread) + h->tf32 pack + x staging ----
        if (t < T_) {
            #pragma unroll
            for (int k = 0; k < 2; k++) {
                const int cr = crow0 + 16 * k;
                float zi = u.p.z1[cr][cu0];
                float zf = u.p.z1[cr][H_ + cu0];
                float zg = u.p.z1[cr][2 * H_ + cu0];
                float zo = u.p.z1[cr][3 * H_ + cu0];
                c1[k] = sigmoidf_(zf) * c1[k] + sigmoidf_(zi) * fmaxf(zg, 0.f);
                float h = sigmoidf_(zo) * fmaxf(c1[k], 0.f);
                uint32_t hi = f2tf32(h);
                u.p.H1p[cr][cu0] = make_uint2(hi, f2tf32(h - __uint_as_float(hi)));
            }
        }
        if (t >= 1) {
            #pragma unroll
            for (int k = 0; k < 2; k++) {
                const int cr = crow0 + 16 * k;
                float zi = u.p.z2[cr][cu0];
                float zf = u.p.z2[cr][H_ + cu0];
                float zg = u.p.z2[cr][2 * H_ + cu0];
                float zo = u.p.z2[cr][3 * H_ + cu0];
                c2[k] = sigmoidf_(zf) * c2[k] + sigmoidf_(zi) * fmaxf(zg, 0.f);
                float h = sigmoidf_(zo) * fmaxf(c2[k], 0.f);
                uint32_t hi = f2tf32(h);
                u.p.H2p[cr][cu0] = make_uint2(hi, f2tf32(h - __uint_as_float(hi)));
            }
        }
        if (t + 1 < T_) {
            const int tn = (t + 2 < T_) ? t + 2 : T_ - 1;
            #pragma unroll
            for (int q = 0; q < 4; q++) {
                if (q < 3 || hasq3) {
                    float v = xv[q] * sc + sh;
                    uint32_t hi = f2tf32(v);
                    u.p.Xp[sr + 10 * q][sf] =
                        make_uint2(hi, f2tf32(v - __uint_as_float(hi)));
                    xv[q] = pxs[q][(size_t)tn * F_];
                }
            }
        }
        __syncthreads();
    }
    #undef LOAD_AFRAG

    // dense head: eo[e,b] = h2(T-1) @ dw[e] + db[e]   (h2 = hi + lo)
    if (tid < LROWS) {
        float acc = db[e];
        #pragma unroll
        for (int j = 0; j < H_; j++) {
            uint2 hv = u.p.H2p[tid][j];
            acc += (__uint_as_float(hv.x) + __uint_as_float(hv.y)) * dw[e * H_ + j];
        }
        g_eo[e * B_ + row0 + tid] = acc;
    }
}

// ===========================================================================
// kC: gate (fc1 row @ gate_w, softmax) + combine -> out[b]   (proven)
// ===========================================================================
__global__ void __launch_bounds__(320) kC_gate_combine(
    const float* __restrict__ GW, const float* __restrict__ GB,
    float* __restrict__ out)
{
    __shared__ float red[10][E_];
    __shared__ float sv[E_];
    __shared__ float ev[E_];
    __shared__ float part[E_];

    const int b = blockIdx.x;
    const int tid = threadIdx.x;
    float acc[E_];
    #pragma unroll
    for (int e = 0; e < E_; e++) acc[e] = 0.f;

    const float* grow = g_fc1 + (size_t)b * D_;
    for (int k = tid; k < D_; k += 320) {
        float gv = grow[k];
        const float4* wp = (const float4*)(GW + (size_t)k * E_);
        float4 w0 = wp[0], w1 = wp[1], w2 = wp[2], w3 = wp[3];
        acc[0]  += gv * w0.x;  acc[1]  += gv * w0.y;
        acc[2]  += gv * w0.z;  acc[3]  += gv * w0.w;
        acc[4]  += gv * w1.x;  acc[5]  += gv * w1.y;
        acc[6]  += gv * w1.z;  acc[7]  += gv * w1.w;
        acc[8]  += gv * w2.x;  acc[9]  += gv * w2.y;
        acc[10] += gv * w2.z;  acc[11] += gv * w2.w;
        acc[12] += gv * w3.x;  acc[13] += gv * w3.y;
        acc[14] += gv * w3.z;  acc[15] += gv * w3.w;
    }
    #pragma unroll
    for (int e = 0; e < E_; e++) {
        #pragma unroll
        for (int off = 16; off > 0; off >>= 1)
            acc[e] += __shfl_down_sync(0xffffffffu, acc[e], off);
    }
    const int warp = tid >> 5, lane = tid & 31;
    if (lane == 0) {
        #pragma unroll
        for (int e = 0; e < E_; e++) red[warp][e] = acc[e];
    }
    __syncthreads();
    if (tid < E_) {
        float s = GB[tid];
        #pragma unroll
        for (int w = 0; w < 10; w++) s += red[w][tid];
        sv[tid] = s;
    }
    __syncthreads();
    if (tid < E_) {
        float m = sv[0];
        #pragma unroll
        for (int e = 1; e < E_; e++) m = fmaxf(m, sv[e]);
        ev[tid] = expf(sv[tid] - m);
    }
    __syncthreads();
    if (tid < E_) {
        float s = 0.f;
        #pragma unroll
        for (int e = 0; e < E_; e++) s += ev[e];
        part[tid] = (ev[tid] / s) * g_eo[tid * B_ + b];
    }
    __syncthreads();
    if (tid == 0) {
        float s = 0.f;
        #pragma unroll
        for (int e = 0; e < E_; e++) s += part[e];
        out[b] = s;
    }
}

// ---------------------------------------------------------------------------
extern "C" void kernel_launch(void* const* d_in, const int* in_sizes, int n_in,
                              void* d_out, int out_size)
{
    const float* x        = (const float*)d_in[0];
    const float* bn_gamma = (const float*)d_in[1];
    const float* bn_beta  = (const float*)d_in[2];
    const float* bn_mean  = (const float*)d_in[3];
    const float* bn_var   = (const float*)d_in[4];
    const float* k1       = (const float*)d_in[5];
    const float* r1       = (const float*)d_in[6];
    const float* b1       = (const float*)d_in[7];
    const float* k2       = (const float*)d_in[8];
    const float* r2       = (const float*)d_in[9];
    const float* b2       = (const float*)d_in[10];
    const float* dw       = (const float*)d_in[11];
    const float* db       = (const float*)d_in[12];
    const float* fc1_w    = (const float*)d_in[13];
    const float* fc1_b    = (const float*)d_in[14];
    const float* gate_w   = (const float*)d_in[15];
    const float* gate_b   = (const float*)d_in[16];
    float* out = (float*)d_out;

    kFat<<<FC1_BLOCKS + LSTM_BLOCKS, 320>>>(
        x, fc1_w, fc1_b, bn_gamma, bn_beta, bn_mean, bn_var,
        k1, r1, b1, k2, r2, b2, dw, db);

    kC_gate_combine<<<B_, 320>>>(gate_w, gate_b, out);
}